// round 10
// baseline (speedup 1.0000x reference)
#include <cuda_runtime.h>
#include <cuda_bf16.h>
#include <cstdint>

// Problem constants
#define PB   64       // batch (cells)
#define PT   64       // num TFs
#define PP   21000    // total peaks
#define PG   2000     // genes
#define PH   3000     // NUM_GOS*GO_DIM
#define PNO  7        // n_out

// d_out layout: x_cat [64*2000] | h [64*3000] | out [64*7]
#define OFF_XCAT 0
#define OFF_H    (PB*PG)
#define OFF_OUT  (PB*PG + PB*PH)

#define G1_NSPLIT 12
#define G1_KSLICE 168    // 11 slices of 168 + last 152 = 2000

// scratch (device globals — no allocation allowed).
// RULE (learned R4-R7): NEVER pass these as kernel arguments from host code —
// the host-side shadow symbol gets passed instead, and on GB300 (ATS,
// pageableMemoryAccess=1) the GPU silently reads the zero-filled HOST copy
// instead of faulting. Reference them directly inside device code only.
__device__ float g_xcat_pre[PB*PG];              // segment sums, pre-bias
__device__ float g_At[PG*PB];                    // x_cat transposed [k=2000][m=64]
__device__ float g_hpre[G1_NSPLIT*PB*PH];        // GEMM1 k-split slabs

// ---------------------------------------------------------------------------
// init: zero the atomic accumulator
// ---------------------------------------------------------------------------
__global__ void init_kernel() {
    int i = blockIdx.x * blockDim.x + threadIdx.x;
    if (i < PB*PG) g_xcat_pre[i] = 0.0f;
}

// ---------------------------------------------------------------------------
// Kernel 1: per-peak dot over TFs + ragged per-gene reduction.
//   grid = (165, 8, 2), block = 128. Each block: 128 peaks x 8 batch x 32 TFs
//   (t-split via grid.z halves block duration -> smaller wave-quant tail).
//   W chunk staged in shared transposed (17KB smem).
// ---------------------------------------------------------------------------
#define PK_PC 128
#define PK_BG 8
#define PK_TCH 32
#define WS_LD 129   // pad: conflict-free STS+LDS

__global__ __launch_bounds__(PK_PC) void peak_kernel(
    const float* __restrict__ x,        // [B,T,P]
    const float* __restrict__ Wp,       // [P,T]
    const int*   __restrict__ gene_ids) // [P]
{
    __shared__ float Ws[PK_TCH * WS_LD];   // [t_local][peak] padded
    __shared__ float vals[PK_PC];

    const int tid = threadIdx.x;
    const int p0  = blockIdx.x * PK_PC;
    const int b0  = blockIdx.y * PK_BG;
    const int tc  = blockIdx.z * PK_TCH;   // this block's 32-TF chunk
    const int p   = p0 + tid;
    const bool valid = (p < PP);

    // gene run structure (leader = first peak of a gene within this chunk)
    int g = 0, runlen = 0;
    bool leader = false;
    if (valid) {
        g = gene_ids[p];
        leader = (tid == 0) || (gene_ids[p-1] != g);
        if (leader) {
            int maxr = min(PK_PC - tid, PP - p);
            runlen = 1;
            while (runlen < maxr && gene_ids[p + runlen] == g) runlen++;
        }
    }

    // stage W chunk [tc, tc+32) transposed. 1024 float4 loads, 8/thread.
    #pragma unroll
    for (int it = 0; it < 8; it++) {
        int q  = tid + it * PK_PC;
        int r  = q >> 3;             // peak row 0..127
        int cq = q & 7;              // quad 0..7 within 32-t chunk
        if (p0 + r < PP) {
            float4 v = *(const float4*)(Wp + (long)(p0 + r) * PT + tc + cq * 4);
            Ws[(cq*4+0) * WS_LD + r] = v.x;
            Ws[(cq*4+1) * WS_LD + r] = v.y;
            Ws[(cq*4+2) * WS_LD + r] = v.z;
            Ws[(cq*4+3) * WS_LD + r] = v.w;
        }
    }
    __syncthreads();

    float acc[PK_BG];
    #pragma unroll
    for (int bi = 0; bi < PK_BG; bi++) acc[bi] = 0.0f;

    if (valid) {
        #pragma unroll
        for (int sub = 0; sub < PK_TCH; sub += 16) {
            float w[16];
            #pragma unroll
            for (int i = 0; i < 16; i++) w[i] = Ws[(sub + i) * WS_LD + tid];
            const float* xb = x + (long)(tc + sub) * PP + p;
            #pragma unroll
            for (int bi = 0; bi < PK_BG; bi++) {
                const float* xr = xb + (long)(b0 + bi) * PT * PP;
                float s = 0.0f;
                #pragma unroll
                for (int i = 0; i < 16; i++)      // MLP = 16
                    s += xr[(long)i * PP] * w[i];
                acc[bi] += s;
            }
        }
    }
    __syncthreads();

    // segmented reduction + one atomic per gene-run per b
    for (int bi = 0; bi < PK_BG; bi++) {
        vals[tid] = valid ? acc[bi] : 0.0f;
        __syncthreads();
        if (leader) {
            float s = 0.0f;
            for (int r = 0; r < runlen; r++) s += vals[tid + r];
            atomicAdd(&g_xcat_pre[(b0 + bi) * PG + g], s);
        }
        __syncthreads();
    }
}

// ---------------------------------------------------------------------------
// x_cat = relu(pre + b_genes) -> d_out AND transposed copy for GEMM1
// ---------------------------------------------------------------------------
__global__ void xcat_kernel(const float* __restrict__ b_genes, float* __restrict__ out)
{
    int i = blockIdx.x * blockDim.x + threadIdx.x;
    if (i < PB*PG) {
        int m = i / PG, g = i % PG;
        float v = fmaxf(g_xcat_pre[i] + b_genes[g], 0.0f);
        out[OFF_XCAT + i] = v;
        g_At[g * PB + m]  = v;
    }
}

// ---------------------------------------------------------------------------
// GEMM1: hpre_slab[split] = At^T[64,kc] @ W1[kc,3000]
//   grid = (24, 12) = 288 blocks (~2/SM), block = 256.
//   Block tile 64(M) x 128(N), KC=16 with zero-fill predication on the
//   partial last tile of each k-slice. Thread tile 4x8. LDG->reg->STS
//   single-buffer pipeline. A from g_At (device symbol, NOT a host arg).
// ---------------------------------------------------------------------------
#define G1_KC 16
#define G1_NT 128

__global__ __launch_bounds__(256) void gemm1_kernel(
    const float* __restrict__ W1)       // [2000][3000]
{
    __shared__ __align__(16) float As[G1_KC][PB];     // 4 KB
    __shared__ __align__(16) float Bs[G1_KC][G1_NT];  // 8 KB

    const float* At = g_At;             // device-side symbol reference

    const int tid = threadIdx.x;
    const int tx = tid & 15;          // n-group: cols tx*4 and 64+tx*4
    const int ty = tid >> 4;          // m-group: rows ty*4..ty*4+3
    const int jt = blockIdx.x * G1_NT;
    const int split = blockIdx.y;
    const int kbase = split * G1_KSLICE;            // 168*11 + 152 = 2000
    const int kend  = min(kbase + G1_KSLICE, PG);
    const int ntiles = (kend - kbase + G1_KC - 1) / G1_KC;  // 11 or 10

    // per-thread load slots
    const int a_kk = tid >> 4;                      // 0..15
    const int a_m  = (tid & 15) * 4;                // 0..60
    const int b_kk = tid >> 5;                      // 0..7 (rows b_kk and 8+b_kk)
    const int b_j  = (tid & 31) * 4;                // 0..124
    const bool b_ok = (jt + b_j + 4 <= PH);

    const float4 z4 = make_float4(0.f, 0.f, 0.f, 0.f);
    float4 aReg, bReg0, bReg1;
    auto fetch = [&](int kt) {
        int k0 = kbase + kt * G1_KC;
        aReg  = (k0 + a_kk < kend)
              ? *(const float4*)(At + (long)(k0 + a_kk) * PB + a_m) : z4;
        bReg0 = (b_ok && k0 + b_kk < kend)
              ? *(const float4*)(W1 + (long)(k0 + b_kk) * PH + jt + b_j) : z4;
        bReg1 = (b_ok && k0 + 8 + b_kk < kend)
              ? *(const float4*)(W1 + (long)(k0 + 8 + b_kk) * PH + jt + b_j) : z4;
    };

    float acc[4][8];
    #pragma unroll
    for (int mm = 0; mm < 4; mm++)
        #pragma unroll
        for (int c = 0; c < 8; c++) acc[mm][c] = 0.0f;

    fetch(0);

    for (int kt = 0; kt < ntiles; kt++) {
        // stage current tile registers -> smem
        *(float4*)&As[a_kk][a_m]       = aReg;
        *(float4*)&Bs[b_kk][b_j]       = bReg0;
        *(float4*)&Bs[8 + b_kk][b_j]   = bReg1;
        __syncthreads();

        // prefetch next tile into registers (overlaps with compute below)
        if (kt + 1 < ntiles) fetch(kt + 1);

        #pragma unroll
        for (int kk = 0; kk < G1_KC; kk++) {
            float4 a  = *(const float4*)&As[kk][ty * 4];
            float4 bl = *(const float4*)&Bs[kk][tx * 4];
            float4 bh = *(const float4*)&Bs[kk][64 + tx * 4];
            float am[4] = {a.x, a.y, a.z, a.w};
            float bj[8] = {bl.x, bl.y, bl.z, bl.w, bh.x, bh.y, bh.z, bh.w};
            #pragma unroll
            for (int mm = 0; mm < 4; mm++)
                #pragma unroll
                for (int c = 0; c < 8; c++)
                    acc[mm][c] += am[mm] * bj[c];
        }
        __syncthreads();   // compute done before smem is overwritten next iter
    }

    // epilogue: pure float4 stores into this split's private slab
    float* slab = g_hpre + (long)split * PB * PH;
    #pragma unroll
    for (int mm = 0; mm < 4; mm++) {
        int m = ty * 4 + mm;
        int j0 = jt + tx * 4;
        if (j0 + 4 <= PH)
            *(float4*)&slab[(long)m * PH + j0] =
                make_float4(acc[mm][0], acc[mm][1], acc[mm][2], acc[mm][3]);
        int j1 = jt + 64 + tx * 4;
        if (j1 + 4 <= PH)
            *(float4*)&slab[(long)m * PH + j1] =
                make_float4(acc[mm][4], acc[mm][5], acc[mm][6], acc[mm][7]);
    }
}

// ---------------------------------------------------------------------------
// Fused tail: h = relu(sum_slabs + b1) -> d_out[OFF_H:], and
//             out[b,:] = h[b,:] @ W2 + b2 -> d_out[OFF_OUT:].
//   grid = 64 (one block per batch row), block = 512.
// ---------------------------------------------------------------------------
__global__ __launch_bounds__(512) void tail_kernel(
    const float* __restrict__ b1,
    const float* __restrict__ W2,       // [3000,7]
    const float* __restrict__ b2,
    float* __restrict__ out)            // full d_out base
{
    const int b = blockIdx.x;
    const int tid = threadIdx.x;
    float acc[PNO] = {};

    for (int k = tid; k < PH; k += 512) {
        float v = b1[k];
        #pragma unroll
        for (int s = 0; s < G1_NSPLIT; s++)
            v += g_hpre[(long)s * (PB*PH) + b * PH + k];
        v = fmaxf(v, 0.0f);
        out[OFF_H + b * PH + k] = v;
        #pragma unroll
        for (int j = 0; j < PNO; j++) acc[j] += v * W2[k * PNO + j];
    }

    #pragma unroll
    for (int j = 0; j < PNO; j++)
        #pragma unroll
        for (int off = 16; off > 0; off >>= 1)
            acc[j] += __shfl_down_sync(0xFFFFFFFFu, acc[j], off);

    __shared__ float red[16][PNO];
    int wid = tid >> 5, lid = tid & 31;
    if (lid == 0)
        for (int j = 0; j < PNO; j++) red[wid][j] = acc[j];
    __syncthreads();
    if (tid < PNO) {
        float s = b2[tid];
        #pragma unroll
        for (int w = 0; w < 16; w++) s += red[w][tid];
        out[OFF_OUT + b * PNO + tid] = s;
    }
}

// ---------------------------------------------------------------------------
extern "C" void kernel_launch(void* const* d_in, const int* in_sizes, int n_in,
                              void* d_out, int out_size)
{
    const float* x        = (const float*)d_in[0]; // [64,64,21000]
    const float* W_peaks  = (const float*)d_in[1]; // [21000,64]
    const float* b_genes  = (const float*)d_in[2]; // [2000]
    const float* W1       = (const float*)d_in[3]; // [2000,3000]
    const float* b1       = (const float*)d_in[4]; // [3000]
    const float* W2       = (const float*)d_in[5]; // [3000,7]
    const float* b2       = (const float*)d_in[6]; // [7]
    const int*   gene_ids = (const int*)  d_in[7]; // [21000]
    float* out = (float*)d_out;

    // 1. zero the atomic accumulator
    init_kernel<<<(PB*PG + 255) / 256, 256>>>();

    // 2. peak dot + segment sum (t-split via grid.z)
    dim3 pk_grid((PP + PK_PC - 1) / PK_PC, PB / PK_BG, PT / PK_TCH); // (165,8,2)
    peak_kernel<<<pk_grid, PK_PC>>>(x, W_peaks, gene_ids);

    // 3. x_cat finalize -> d_out + transposed copy (device global, written on device)
    xcat_kernel<<<(PB*PG + 255) / 256, 256>>>(b_genes, out);

    // 4. GEMM1 (k-split slabs, no atomics; A referenced via device symbol)
    dim3 g1_grid((PH + G1_NT - 1) / G1_NT, G1_NSPLIT);    // (24, 12)
    gemm1_kernel<<<g1_grid, 256>>>(W1);

    // 5. fused h finalize + GEMM2 -> d_out
    tail_kernel<<<PB, 512>>>(b1, W2, b2, out);
}

// round 11
// speedup vs baseline: 1.3652x; 1.3652x over previous
#include <cuda_runtime.h>
#include <cuda_bf16.h>
#include <cstdint>

// Problem constants
#define PB   64       // batch (cells)
#define PT   64       // num TFs
#define PP   21000    // total peaks
#define PG   2000     // genes
#define PH   3000     // NUM_GOS*GO_DIM
#define PNO  7        // n_out

// d_out layout: x_cat [64*2000] | h [64*3000] | out [64*7]
#define OFF_XCAT 0
#define OFF_H    (PB*PG)
#define OFF_OUT  (PB*PG + PB*PH)

#define G1_NSPLIT 6      // measured best (R8); 12 regressed (R10)

// scratch (device globals — no allocation allowed).
// RULE (learned R4-R7): NEVER pass these as kernel arguments from host code —
// the host-side shadow symbol gets passed instead, and on GB300 (ATS,
// pageableMemoryAccess=1) the GPU silently reads the zero-filled HOST copy
// instead of faulting. Reference them directly inside device code only.
__device__ float g_xcat_pre[PB*PG];              // segment sums, pre-bias
__device__ float g_At[PG*PB];                    // x_cat transposed [k=2000][m=64]
__device__ float g_hpre[G1_NSPLIT*PB*PH];        // GEMM1 k-split slabs

// ---------------------------------------------------------------------------
// init: zero the atomic accumulator
// ---------------------------------------------------------------------------
__global__ void init_kernel() {
    int i = blockIdx.x * blockDim.x + threadIdx.x;
    if (i < PB*PG) g_xcat_pre[i] = 0.0f;
}

// ---------------------------------------------------------------------------
// Kernel 1 (R8 config — measured best): per-peak dot over TFs + ragged
//   per-gene reduction. grid = (165, 8), block = 128.
//   Each block: 128 peaks x 8 batch rows, full 64-TF loop in 32-TF chunks.
// ---------------------------------------------------------------------------
#define PK_PC 128
#define PK_BG 8
#define PK_TCH 32
#define WS_LD 129   // pad: conflict-free STS+LDS

__global__ __launch_bounds__(PK_PC) void peak_kernel(
    const float* __restrict__ x,        // [B,T,P]
    const float* __restrict__ Wp,       // [P,T]
    const int*   __restrict__ gene_ids) // [P]
{
    __shared__ float Ws[PK_TCH * WS_LD];   // [t_local][peak] padded
    __shared__ float vals[PK_PC];

    const int tid = threadIdx.x;
    const int p0  = blockIdx.x * PK_PC;
    const int b0  = blockIdx.y * PK_BG;
    const int p   = p0 + tid;
    const bool valid = (p < PP);

    // gene run structure (leader = first peak of a gene within this chunk)
    int g = 0, runlen = 0;
    bool leader = false;
    if (valid) {
        g = gene_ids[p];
        leader = (tid == 0) || (gene_ids[p-1] != g);
        if (leader) {
            int maxr = min(PK_PC - tid, PP - p);
            runlen = 1;
            while (runlen < maxr && gene_ids[p + runlen] == g) runlen++;
        }
    }

    float acc[PK_BG];
    #pragma unroll
    for (int bi = 0; bi < PK_BG; bi++) acc[bi] = 0.0f;

    for (int tc = 0; tc < PT; tc += PK_TCH) {
        // stage W chunk [tc, tc+32) transposed. 1024 float4 loads, 8/thread.
        #pragma unroll
        for (int it = 0; it < 8; it++) {
            int q  = tid + it * PK_PC;
            int r  = q >> 3;             // peak row 0..127
            int cq = q & 7;              // quad 0..7 within 32-t chunk
            if (p0 + r < PP) {
                float4 v = *(const float4*)(Wp + (long)(p0 + r) * PT + tc + cq * 4);
                Ws[(cq*4+0) * WS_LD + r] = v.x;
                Ws[(cq*4+1) * WS_LD + r] = v.y;
                Ws[(cq*4+2) * WS_LD + r] = v.z;
                Ws[(cq*4+3) * WS_LD + r] = v.w;
            }
        }
        __syncthreads();

        if (valid) {
            #pragma unroll
            for (int sub = 0; sub < PK_TCH; sub += 16) {
                float w[16];
                #pragma unroll
                for (int i = 0; i < 16; i++) w[i] = Ws[(sub + i) * WS_LD + tid];
                const float* xb = x + (long)(tc + sub) * PP + p;
                #pragma unroll
                for (int bi = 0; bi < PK_BG; bi++) {
                    const float* xr = xb + (long)(b0 + bi) * PT * PP;
                    float s = 0.0f;
                    #pragma unroll
                    for (int i = 0; i < 16; i++)      // MLP = 16
                        s += xr[(long)i * PP] * w[i];
                    acc[bi] += s;
                }
            }
        }
        __syncthreads();
    }

    // segmented reduction + one atomic per gene-run
    for (int bi = 0; bi < PK_BG; bi++) {
        vals[tid] = valid ? acc[bi] : 0.0f;
        __syncthreads();
        if (leader) {
            float s = 0.0f;
            for (int r = 0; r < runlen; r++) s += vals[tid + r];
            atomicAdd(&g_xcat_pre[(b0 + bi) * PG + g], s);
        }
        __syncthreads();
    }
}

// ---------------------------------------------------------------------------
// x_cat = relu(pre + b_genes) -> d_out AND transposed copy for GEMM1
// ---------------------------------------------------------------------------
__global__ void xcat_kernel(const float* __restrict__ b_genes, float* __restrict__ out)
{
    int i = blockIdx.x * blockDim.x + threadIdx.x;
    if (i < PB*PG) {
        int m = i / PG, g = i % PG;
        float v = fmaxf(g_xcat_pre[i] + b_genes[g], 0.0f);
        out[OFF_XCAT + i] = v;
        g_At[g * PB + m]  = v;
    }
}

// ---------------------------------------------------------------------------
// GEMM1 (R8 config — measured best): hpre_slab[split] = At^T[64,kc] @ W1[kc,3000]
//   grid = (24, 6), block = 256. Block tile 64(M) x 128(N), KC=16,
//   thread tile 4x8. LDG->reg->STS single-buffer pipeline (prefetch next
//   tile into registers during compute). A from g_At (device symbol).
// ---------------------------------------------------------------------------
#define G1_KC 16
#define G1_NT 128

__global__ __launch_bounds__(256) void gemm1_kernel(
    const float* __restrict__ W1)       // [2000][3000]
{
    __shared__ __align__(16) float As[G1_KC][PB];     // 4 KB
    __shared__ __align__(16) float Bs[G1_KC][G1_NT];  // 8 KB

    const float* At = g_At;             // device-side symbol reference

    const int tid = threadIdx.x;
    const int tx = tid & 15;          // n-group: cols tx*4 and 64+tx*4
    const int ty = tid >> 4;          // m-group: rows ty*4..ty*4+3
    const int jt = blockIdx.x * G1_NT;
    const int split = blockIdx.y;
    const int kbase = split * 336;                  // 5x336 + 320 = 2000
    const int kc = min(336, PG - kbase);
    const int ntiles = kc / G1_KC;                  // 21 or 20

    // per-thread load slots
    const int a_kk = tid >> 4;                      // 0..15
    const int a_m  = (tid & 15) * 4;                // 0..60
    const int b_kk = tid >> 5;                      // 0..7 (rows b_kk and 8+b_kk)
    const int b_j  = (tid & 31) * 4;                // 0..124
    const bool b_ok = (jt + b_j + 4 <= PH);

    float4 aReg, bReg0, bReg1;
    auto fetch = [&](int kt) {
        int k0 = kbase + kt * G1_KC;
        aReg = *(const float4*)(At + (long)(k0 + a_kk) * PB + a_m);
        if (b_ok) {
            bReg0 = *(const float4*)(W1 + (long)(k0 + b_kk)     * PH + jt + b_j);
            bReg1 = *(const float4*)(W1 + (long)(k0 + 8 + b_kk) * PH + jt + b_j);
        } else {
            bReg0 = make_float4(0.f, 0.f, 0.f, 0.f);
            bReg1 = make_float4(0.f, 0.f, 0.f, 0.f);
        }
    };

    float acc[4][8];
    #pragma unroll
    for (int mm = 0; mm < 4; mm++)
        #pragma unroll
        for (int c = 0; c < 8; c++) acc[mm][c] = 0.0f;

    fetch(0);

    for (int kt = 0; kt < ntiles; kt++) {
        // stage current tile registers -> smem
        *(float4*)&As[a_kk][a_m]       = aReg;
        *(float4*)&Bs[b_kk][b_j]       = bReg0;
        *(float4*)&Bs[8 + b_kk][b_j]   = bReg1;
        __syncthreads();

        // prefetch next tile into registers (overlaps with compute below)
        if (kt + 1 < ntiles) fetch(kt + 1);

        #pragma unroll
        for (int kk = 0; kk < G1_KC; kk++) {
            float4 a  = *(const float4*)&As[kk][ty * 4];
            float4 bl = *(const float4*)&Bs[kk][tx * 4];
            float4 bh = *(const float4*)&Bs[kk][64 + tx * 4];
            float am[4] = {a.x, a.y, a.z, a.w};
            float bj[8] = {bl.x, bl.y, bl.z, bl.w, bh.x, bh.y, bh.z, bh.w};
            #pragma unroll
            for (int mm = 0; mm < 4; mm++)
                #pragma unroll
                for (int c = 0; c < 8; c++)
                    acc[mm][c] += am[mm] * bj[c];
        }
        __syncthreads();   // compute done before smem is overwritten next iter
    }

    // epilogue: pure float4 stores into this split's private slab
    float* slab = g_hpre + (long)split * PB * PH;
    #pragma unroll
    for (int mm = 0; mm < 4; mm++) {
        int m = ty * 4 + mm;
        int j0 = jt + tx * 4;
        if (j0 + 4 <= PH)
            *(float4*)&slab[(long)m * PH + j0] =
                make_float4(acc[mm][0], acc[mm][1], acc[mm][2], acc[mm][3]);
        int j1 = jt + 64 + tx * 4;
        if (j1 + 4 <= PH)
            *(float4*)&slab[(long)m * PH + j1] =
                make_float4(acc[mm][4], acc[mm][5], acc[mm][6], acc[mm][7]);
    }
}

// ---------------------------------------------------------------------------
// Fused tail: h = relu(sum_slabs + b1) -> d_out[OFF_H:], and
//             out[b,:] = h[b,:] @ W2 + b2 -> d_out[OFF_OUT:].
//   grid = 64 (one block per batch row), block = 512.
// ---------------------------------------------------------------------------
__global__ __launch_bounds__(512) void tail_kernel(
    const float* __restrict__ b1,
    const float* __restrict__ W2,       // [3000,7]
    const float* __restrict__ b2,
    float* __restrict__ out)            // full d_out base
{
    const int b = blockIdx.x;
    const int tid = threadIdx.x;
    float acc[PNO] = {};

    for (int k = tid; k < PH; k += 512) {
        float v = b1[k];
        #pragma unroll
        for (int s = 0; s < G1_NSPLIT; s++)
            v += g_hpre[(long)s * (PB*PH) + b * PH + k];
        v = fmaxf(v, 0.0f);
        out[OFF_H + b * PH + k] = v;
        #pragma unroll
        for (int j = 0; j < PNO; j++) acc[j] += v * W2[k * PNO + j];
    }

    #pragma unroll
    for (int j = 0; j < PNO; j++)
        #pragma unroll
        for (int off = 16; off > 0; off >>= 1)
            acc[j] += __shfl_down_sync(0xFFFFFFFFu, acc[j], off);

    __shared__ float red[16][PNO];
    int wid = tid >> 5, lid = tid & 31;
    if (lid == 0)
        for (int j = 0; j < PNO; j++) red[wid][j] = acc[j];
    __syncthreads();
    if (tid < PNO) {
        float s = b2[tid];
        #pragma unroll
        for (int w = 0; w < 16; w++) s += red[w][tid];
        out[OFF_OUT + b * PNO + tid] = s;
    }
}

// ---------------------------------------------------------------------------
extern "C" void kernel_launch(void* const* d_in, const int* in_sizes, int n_in,
                              void* d_out, int out_size)
{
    const float* x        = (const float*)d_in[0]; // [64,64,21000]
    const float* W_peaks  = (const float*)d_in[1]; // [21000,64]
    const float* b_genes  = (const float*)d_in[2]; // [2000]
    const float* W1       = (const float*)d_in[3]; // [2000,3000]
    const float* b1       = (const float*)d_in[4]; // [3000]
    const float* W2       = (const float*)d_in[5]; // [3000,7]
    const float* b2       = (const float*)d_in[6]; // [7]
    const int*   gene_ids = (const int*)  d_in[7]; // [21000]
    float* out = (float*)d_out;

    // 1. zero the atomic accumulator
    init_kernel<<<(PB*PG + 255) / 256, 256>>>();

    // 2. peak dot + segment sum (R8 config)
    dim3 pk_grid((PP + PK_PC - 1) / PK_PC, PB / PK_BG);   // (165, 8)
    peak_kernel<<<pk_grid, PK_PC>>>(x, W_peaks, gene_ids);

    // 3. x_cat finalize -> d_out + transposed copy (device global, written on device)
    xcat_kernel<<<(PB*PG + 255) / 256, 256>>>(b_genes, out);

    // 4. GEMM1 (k-split slabs, no atomics; A referenced via device symbol)
    dim3 g1_grid((PH + G1_NT - 1) / G1_NT, G1_NSPLIT);    // (24, 6)
    gemm1_kernel<<<g1_grid, 256>>>(W1);

    // 5. fused h finalize + GEMM2 -> d_out
    tail_kernel<<<PB, 512>>>(b1, W2, b2, out);
}